// round 15
// baseline (speedup 1.0000x reference)
#include <cuda_runtime.h>
#include <cuda_fp16.h>
#include <math.h>

#define NNODES 100000
#define NEDGES 1600000
#define NEG 0.2f
#define GM_ROWS 128
#define CS_BLOCKS 296
#define CS_THREADS 512

// ---------------- scratch (device globals; no allocation allowed) ----------
__device__ __half g_w1h[128 * 128];               // W1 fp16 transposed [n][k]
__device__ __half g_w2h[32 * 128];                // W2 fp16 transposed [n][k]
__device__ __half g_h1[NNODES * 128];             // layer1 features fp16
__device__ float  g_el1[NNODES * 4];
__device__ float  g_er1[NNODES * 4];
__device__ __half g_x2h[(NNODES + GM_ROWS) * 128];  // layer1 out (elu) fp16, padded
__device__ __half g_h2[NNODES * 32];              // layer2 features fp16
__device__ float  g_el2[NNODES];
__device__ float  g_er2[NNODES];
__device__ int    g_deg[NNODES];
__device__ int    g_rowptr[NNODES + 1];
__device__ int    g_cursor[NNODES];
__device__ int    g_csrc[NEDGES + 64];            // padded; pad never written (=0)
__device__ int    g_cdst[NEDGES + 64];            // padded
__device__ float4 g_w1e[NEDGES + 16];             // layer1 edge weights (4 heads), padded
__device__ float  g_w2e[NEDGES + 64];             // layer2 edge weights, padded
__device__ int    g_bsum[CS_BLOCKS];
__device__ int    g_flags[304];   // [0..295] block flags, [300] sync1

__device__ __forceinline__ unsigned packh2(float a, float b) {
    __half2 h = __floats2half2_rn(a, b);
    return *(unsigned*)&h;
}
__device__ __forceinline__ float edgew(float e) {
    e = (e > 0.f) ? e : NEG * e;
    return __expf(fminf(e, 60.f));
}
__device__ __forceinline__ float elu1(float x) {
    return x > 0.f ? x : (__expf(x) - 1.f);
}

// ---------------- setup -----------------------------------------------------
__global__ __launch_bounds__(256) void setup_zero_kernel() {
    int idx = blockIdx.x * 256 + threadIdx.x;
    int stride = gridDim.x * 256;
    for (int i = idx; i < 25076; i += stride) {
        if (i < 25000) ((int4*)g_deg)[i] = make_int4(0, 0, 0, 0);
        else           ((int4*)g_flags)[i - 25000] = make_int4(0, 0, 0, 0);
    }
}
__global__ __launch_bounds__(256) void setup_conv_kernel(const float* __restrict__ W1,
                                                         const float* __restrict__ W2) {
    int idx = blockIdx.x * 256 + threadIdx.x;
    int stride = gridDim.x * 256;
    for (int i = idx; i < 16384 + 4096; i += stride) {
        if (i < 16384) {
            int k = i >> 7, n = i & 127;
            g_w1h[n * 128 + k] = __float2half_rn(W1[i]);
        } else {
            int j = i - 16384;
            int k = j >> 5, n = j & 31;          // W2: [128][32]
            g_w2h[n * 128 + k] = __float2half_rn(W2[j]);
        }
    }
}

// ---------------- GEMM1 via HMMA: A direct from fp32 x ----------------------
#define WS_STRIDE 136

__global__ __launch_bounds__(256) void gemm1_kernel(
    const float* __restrict__ x, const float* __restrict__ al,
    const float* __restrict__ ar) {
    __shared__ __half ws[128 * WS_STRIDE];  // 34.8 KB: ws[n][k] = W1^T
    int tid = threadIdx.x;
    int nb = blockIdx.x * GM_ROWS;

    for (int i = tid; i < 2048; i += 256) {
        int row = i >> 4, c = i & 15;
        *(uint4*)(ws + row * WS_STRIDE + c * 8) =
            *(const uint4*)(g_w1h + row * 128 + c * 8);
    }
    __syncthreads();

    int l = tid & 31, w = tid >> 5;
    int g4 = l >> 2, q = l & 3;
    int r0 = nb + w * 16 + g4;
    int r1 = r0 + 8;
    const float* xr0 = x + (size_t)(r0 < NNODES ? r0 : NNODES - 1) * 128;
    const float* xr1 = x + (size_t)(r1 < NNODES ? r1 : NNODES - 1) * 128;

    float d[16][4];
#pragma unroll
    for (int nt = 0; nt < 16; ++nt)
#pragma unroll
        for (int c = 0; c < 4; ++c) d[nt][c] = 0.f;

#pragma unroll
    for (int ks = 0; ks < 8; ++ks) {
        int kb = ks * 16 + q * 2;
        float2 f0 = *(const float2*)(xr0 + kb);
        float2 f1 = *(const float2*)(xr1 + kb);
        float2 f2 = *(const float2*)(xr0 + kb + 8);
        float2 f3 = *(const float2*)(xr1 + kb + 8);
        unsigned a0 = packh2(f0.x, f0.y);
        unsigned a1 = packh2(f1.x, f1.y);
        unsigned a2 = packh2(f2.x, f2.y);
        unsigned a3 = packh2(f3.x, f3.y);
#pragma unroll
        for (int nt = 0; nt < 16; ++nt) {
            const __half* wb = ws + (nt * 8 + g4) * WS_STRIDE + kb;
            unsigned b0 = *(const unsigned*)(wb);
            unsigned b1 = *(const unsigned*)(wb + 8);
            asm volatile(
                "mma.sync.aligned.m16n8k16.row.col.f32.f16.f16.f32 "
                "{%0,%1,%2,%3}, {%4,%5,%6,%7}, {%8,%9}, {%0,%1,%2,%3};"
                : "+f"(d[nt][0]), "+f"(d[nt][1]), "+f"(d[nt][2]), "+f"(d[nt][3])
                : "r"(a0), "r"(a1), "r"(a2), "r"(a3), "r"(b0), "r"(b1));
        }
    }

#pragma unroll
    for (int h = 0; h < 4; ++h) {
        float pel0 = 0.f, per0 = 0.f, pel1 = 0.f, per1 = 0.f;
#pragma unroll
        for (int t = 0; t < 4; ++t) {
            int nt = h * 4 + t;
            int c0 = nt * 8 + q * 2;
            float alv0 = __ldg(&al[c0]), alv1 = __ldg(&al[c0 + 1]);
            float arv0 = __ldg(&ar[c0]), arv1 = __ldg(&ar[c0 + 1]);
            pel0 += d[nt][0] * alv0 + d[nt][1] * alv1;
            per0 += d[nt][0] * arv0 + d[nt][1] * arv1;
            pel1 += d[nt][2] * alv0 + d[nt][3] * alv1;
            per1 += d[nt][2] * arv0 + d[nt][3] * arv1;
        }
#pragma unroll
        for (int o = 1; o < 4; o <<= 1) {
            pel0 += __shfl_xor_sync(0xffffffffu, pel0, o);
            per0 += __shfl_xor_sync(0xffffffffu, per0, o);
            pel1 += __shfl_xor_sync(0xffffffffu, pel1, o);
            per1 += __shfl_xor_sync(0xffffffffu, per1, o);
        }
        if (q == 0) {
            if (r0 < NNODES) { g_el1[r0 * 4 + h] = pel0; g_er1[r0 * 4 + h] = per0; }
            if (r1 < NNODES) { g_el1[r1 * 4 + h] = pel1; g_er1[r1 * 4 + h] = per1; }
        }
    }
#pragma unroll
    for (int nt = 0; nt < 16; ++nt) {
        int c0 = nt * 8 + q * 2;
        if (r0 < NNODES)
            ((__half2*)g_h1)[(size_t)r0 * 64 + (c0 >> 1)] =
                __floats2half2_rn(d[nt][0], d[nt][1]);
        if (r1 < NNODES)
            ((__half2*)g_h1)[(size_t)r1 * 64 + (c0 >> 1)] =
                __floats2half2_rn(d[nt][2], d[nt][3]);
    }
}

// ---------------- count + scan (resident grid, one spin-sync) ---------------
__global__ __launch_bounds__(CS_THREADS) void cs_kernel(const int* __restrict__ dst) {
    __shared__ int s[CS_THREADS];
    __shared__ int s_off;
    int b = blockIdx.x, tid = threadIdx.x;
    int gt = b * CS_THREADS + tid;
    const int nthreads = CS_BLOCKS * CS_THREADS;

    // phase 1: degree count
    for (int i = gt; i < NEDGES / 4; i += nthreads) {
        int4 d = ((const int4*)dst)[i];
        atomicAdd(&g_deg[d.x], 1);
        atomicAdd(&g_deg[d.y], 1);
        atomicAdd(&g_deg[d.z], 1);
        atomicAdd(&g_deg[d.w], 1);
    }
    __threadfence();
    __syncthreads();
    if (tid == 0) {
        atomicAdd(&g_flags[300], 1);
        while (atomicAdd(&g_flags[300], 0) < CS_BLOCKS) {}
    }
    __syncthreads();

    // phase 2: scan (block b owns elements b*512 .. +511)
    int v = (gt < NNODES) ? g_deg[gt] : 0;
    s[tid] = v;
    if (tid == 0) s_off = 0;
    __syncthreads();
    for (int off = 1; off < CS_THREADS; off <<= 1) {
        int t = (tid >= off) ? s[tid - off] : 0;
        __syncthreads();
        s[tid] += t;
        __syncthreads();
    }
    if (tid == CS_THREADS - 1) {
        g_bsum[b] = s[CS_THREADS - 1];
        __threadfence();
        atomicExch(&g_flags[b], 1);
    }
    if (tid < b) {   // parallel lookback (b < 512)
        while (atomicAdd(&g_flags[tid], 0) == 0) {}
        atomicAdd(&s_off, atomicAdd(&g_bsum[tid], 0));
    }
    __syncthreads();
    if (gt < NNODES) {
        int val = s_off + s[tid];
        g_rowptr[gt + 1] = val;
        if (gt + 1 < NNODES) g_cursor[gt + 1] = val;
    }
    if (gt == 0) { g_rowptr[0] = 0; g_cursor[0] = 0; }
}

// ---------------- fill + layer1 weights (after gemm1 & cs join) -------------
__global__ __launch_bounds__(256) void fillw_kernel(const int* __restrict__ src,
                                                    const int* __restrict__ dst) {
    int i = blockIdx.x * 256 + threadIdx.x;
    if (i >= NEDGES / 4) return;
    int4 d4 = ((const int4*)dst)[i];
    int4 s4 = ((const int4*)src)[i];
    int dd[4] = {d4.x, d4.y, d4.z, d4.w};
    int ss[4] = {s4.x, s4.y, s4.z, s4.w};
#pragma unroll
    for (int e = 0; e < 4; ++e) {
        int d = dd[e], sc = ss[e];
        int p = atomicAdd(&g_cursor[d], 1);
        g_csrc[p] = sc;
        g_cdst[p] = d;
        float4 el = __ldg((const float4*)&g_el1[sc * 4]);
        float4 er = __ldg((const float4*)&g_er1[d * 4]);
        float4 w;
        w.x = edgew(el.x + er.x);
        w.y = edgew(el.y + er.y);
        w.z = edgew(el.z + er.z);
        w.w = edgew(el.w + er.w);
        g_w1e[p] = w;
    }
}

// ---------------- layer2 edge weights (after gemm2), edge-parallel ----------
__global__ __launch_bounds__(256) void w2e_kernel() {
    int i = blockIdx.x * 256 + threadIdx.x;
    if (i < NEDGES / 4) {
        int4 s4 = ((const int4*)g_csrc)[i];
        int4 d4 = ((const int4*)g_cdst)[i];
        float4 w;
        w.x = edgew(__ldg(&g_el2[s4.x]) + __ldg(&g_er2[d4.x]));
        w.y = edgew(__ldg(&g_el2[s4.y]) + __ldg(&g_er2[d4.y]));
        w.z = edgew(__ldg(&g_el2[s4.z]) + __ldg(&g_er2[d4.z]));
        w.w = edgew(__ldg(&g_el2[s4.w]) + __ldg(&g_er2[d4.w]));
        ((float4*)g_w2e)[i] = w;
    }
}

// ---------------- AGG layer1: warp/node, precomputed weights ----------------
__global__ __launch_bounds__(256) void agg1_kernel(const float* __restrict__ b1) {
    int n = (blockIdx.x * 256 + threadIdx.x) >> 5;
    if (n >= NNODES) return;
    int l = threadIdx.x & 31;
    int h = l >> 3;
    int s0 = g_rowptr[n], s1 = g_rowptr[n + 1];
    float4 bv = ((const float4*)b1)[l];
    float4 res = bv;
    if (s1 > s0) {
        float sm = 0.f;
        float4 acc = make_float4(0.f, 0.f, 0.f, 0.f);
        const float* wbase = (const float*)g_w1e;
        const uint2* hbase = (const uint2*)g_h1;
        int s = g_csrc[s0];
        for (int j = s0; j < s1; ++j) {
            int snext = __ldg(&g_csrc[j + 1]);   // padded: unconditional
            float wg = __ldg(&wbase[(size_t)j * 4 + h]);
            uint2 p = hbase[(size_t)s * 32 + l];
            float2 f01 = __half22float2(*(__half2*)&p.x);
            float2 f23 = __half22float2(*(__half2*)&p.y);
            sm += wg;
            acc.x = fmaf(wg, f01.x, acc.x);
            acc.y = fmaf(wg, f01.y, acc.y);
            acc.z = fmaf(wg, f23.x, acc.z);
            acc.w = fmaf(wg, f23.y, acc.w);
            s = snext;
        }
        float inv = 1.f / sm;
        res = make_float4(fmaf(acc.x, inv, bv.x), fmaf(acc.y, inv, bv.y),
                          fmaf(acc.z, inv, bv.z), fmaf(acc.w, inv, bv.w));
    }
    res.x = elu1(res.x);
    res.y = elu1(res.y);
    res.z = elu1(res.z);
    res.w = elu1(res.w);
    uint2 u;
    u.x = packh2(res.x, res.y);
    u.y = packh2(res.z, res.w);
    ((uint2*)g_x2h)[(size_t)n * 32 + l] = u;
}

// ---------------- GEMM2 via HMMA: h2 = x2 @ W2, fused el2/er2 ---------------
__global__ __launch_bounds__(256) void gemm2_kernel(
    const float* __restrict__ al, const float* __restrict__ ar) {
    __shared__ __half ws[32 * WS_STRIDE];  // 8.7 KB: ws[n][k] = W2^T
    int tid = threadIdx.x;
    int nb = blockIdx.x * GM_ROWS;

    for (int i = tid; i < 512; i += 256) {
        int row = i >> 4, c = i & 15;
        *(uint4*)(ws + row * WS_STRIDE + c * 8) =
            *(const uint4*)(g_w2h + row * 128 + c * 8);
    }
    __syncthreads();

    int l = tid & 31, w = tid >> 5;
    int g4 = l >> 2, q = l & 3;
    int r0 = nb + w * 16 + g4;
    int r1 = r0 + 8;
    const __half* xr0 = g_x2h + (size_t)r0 * 128;
    const __half* xr1 = g_x2h + (size_t)r1 * 128;

    float d[4][4];
#pragma unroll
    for (int nt = 0; nt < 4; ++nt)
#pragma unroll
        for (int c = 0; c < 4; ++c) d[nt][c] = 0.f;

#pragma unroll
    for (int ks = 0; ks < 8; ++ks) {
        int kb = ks * 16 + q * 2;
        unsigned a0 = *(const unsigned*)(xr0 + kb);
        unsigned a1 = *(const unsigned*)(xr1 + kb);
        unsigned a2 = *(const unsigned*)(xr0 + kb + 8);
        unsigned a3 = *(const unsigned*)(xr1 + kb + 8);
#pragma unroll
        for (int nt = 0; nt < 4; ++nt) {
            const __half* wb = ws + (nt * 8 + g4) * WS_STRIDE + kb;
            unsigned b0 = *(const unsigned*)(wb);
            unsigned b1 = *(const unsigned*)(wb + 8);
            asm volatile(
                "mma.sync.aligned.m16n8k16.row.col.f32.f16.f16.f32 "
                "{%0,%1,%2,%3}, {%4,%5,%6,%7}, {%8,%9}, {%0,%1,%2,%3};"
                : "+f"(d[nt][0]), "+f"(d[nt][1]), "+f"(d[nt][2]), "+f"(d[nt][3])
                : "r"(a0), "r"(a1), "r"(a2), "r"(a3), "r"(b0), "r"(b1));
        }
    }

    {
        float pel0 = 0.f, per0 = 0.f, pel1 = 0.f, per1 = 0.f;
#pragma unroll
        for (int nt = 0; nt < 4; ++nt) {
            int c0 = nt * 8 + q * 2;
            float alv0 = __ldg(&al[c0]), alv1 = __ldg(&al[c0 + 1]);
            float arv0 = __ldg(&ar[c0]), arv1 = __ldg(&ar[c0 + 1]);
            pel0 += d[nt][0] * alv0 + d[nt][1] * alv1;
            per0 += d[nt][0] * arv0 + d[nt][1] * arv1;
            pel1 += d[nt][2] * alv0 + d[nt][3] * alv1;
            per1 += d[nt][2] * arv0 + d[nt][3] * arv1;
        }
#pragma unroll
        for (int o = 1; o < 4; o <<= 1) {
            pel0 += __shfl_xor_sync(0xffffffffu, pel0, o);
            per0 += __shfl_xor_sync(0xffffffffu, per0, o);
            pel1 += __shfl_xor_sync(0xffffffffu, pel1, o);
            per1 += __shfl_xor_sync(0xffffffffu, per1, o);
        }
        if (q == 0) {
            if (r0 < NNODES) { g_el2[r0] = pel0; g_er2[r0] = per0; }
            if (r1 < NNODES) { g_el2[r1] = pel1; g_er2[r1] = per1; }
        }
    }
#pragma unroll
    for (int nt = 0; nt < 4; ++nt) {
        int c0 = nt * 8 + q * 2;
        if (r0 < NNODES)
            ((__half2*)g_h2)[(size_t)r0 * 16 + (c0 >> 1)] =
                __floats2half2_rn(d[nt][0], d[nt][1]);
        if (r1 < NNODES)
            ((__half2*)g_h2)[(size_t)r1 * 16 + (c0 >> 1)] =
                __floats2half2_rn(d[nt][2], d[nt][3]);
    }
}

// ---------------- AGG layer2: warp/node, 4 edges per iteration --------------
__global__ __launch_bounds__(256) void agg2_kernel(const float* __restrict__ b2,
                                                   float* __restrict__ out) {
    int n = (blockIdx.x * 256 + threadIdx.x) >> 5;
    if (n >= NNODES) return;
    int l = threadIdx.x & 31;
    int eo = l >> 3;
    int c4 = l & 7;
    int s0 = g_rowptr[n], s1 = g_rowptr[n + 1];
    float4 bv = ((const float4*)b2)[c4];
    float4 res = bv;
    if (s1 > s0) {
        float sm = 0.f;
        float acc[4];
#pragma unroll
        for (int i = 0; i < 4; ++i) acc[i] = 0.f;
        const uint2* hbase = (const uint2*)g_h2;
        for (int j = s0; j < s1; j += 4) {
            int je = j + eo;
            int se = __ldg(&g_csrc[je]);       // padded
            float wg = __ldg(&g_w2e[je]);      // padded
            if (je >= s1) wg = 0.f;
            uint2 p = __ldg(&hbase[(unsigned)se * 8u + c4]);
            float2 f0 = __half22float2(*(__half2*)&p.x);
            float2 f1 = __half22float2(*(__half2*)&p.y);
            sm += wg;
            acc[0] = fmaf(wg, f0.x, acc[0]);
            acc[1] = fmaf(wg, f0.y, acc[1]);
            acc[2] = fmaf(wg, f1.x, acc[2]);
            acc[3] = fmaf(wg, f1.y, acc[3]);
        }
        sm += __shfl_xor_sync(0xffffffffu, sm, 8);
        sm += __shfl_xor_sync(0xffffffffu, sm, 16);
#pragma unroll
        for (int i = 0; i < 4; ++i) {
            acc[i] += __shfl_xor_sync(0xffffffffu, acc[i], 8);
            acc[i] += __shfl_xor_sync(0xffffffffu, acc[i], 16);
        }
        float inv = 1.f / sm;
        res.x = fmaf(acc[0], inv, bv.x);
        res.y = fmaf(acc[1], inv, bv.y);
        res.z = fmaf(acc[2], inv, bv.z);
        res.w = fmaf(acc[3], inv, bv.w);
    }
    if (eo == 0) {
        ((float4*)out)[(size_t)n * 8 + c4] = res;
    }
}

// ---------------- launch: fork gemm1 path onto a second stream --------------
extern "C" void kernel_launch(void* const* d_in, const int* in_sizes, int n_in,
                              void* d_out, int out_size) {
    const float* x   = (const float*)d_in[0];
    const int*   src = (const int*)d_in[1];
    const int*   dst = (const int*)d_in[2];
    const float* W1  = (const float*)d_in[3];
    const float* al1 = (const float*)d_in[4];
    const float* ar1 = (const float*)d_in[5];
    const float* b1  = (const float*)d_in[6];
    const float* W2  = (const float*)d_in[7];
    const float* al2 = (const float*)d_in[8];
    const float* ar2 = (const float*)d_in[9];
    const float* b2  = (const float*)d_in[10];
    float* out = (float*)d_out;

    // fork-join pair (created per call; NOT destroyed mid-capture — host
    // driver objects only, no device memory)
    cudaStream_t s2;
    cudaStreamCreate(&s2);
    cudaEvent_t eFork, eJoin;
    cudaEventCreateWithFlags(&eFork, cudaEventDisableTiming);
    cudaEventCreateWithFlags(&eJoin, cudaEventDisableTiming);

    cudaEventRecord(eFork, 0);
    cudaStreamWaitEvent(s2, eFork, 0);

    // branch A (s2): weight convert + gemm1  (independent of CSR)
    setup_conv_kernel<<<16, 256, 0, s2>>>(W1, W2);
    gemm1_kernel<<<(NNODES + GM_ROWS - 1) / GM_ROWS, 256, 0, s2>>>(x, al1, ar1);
    cudaEventRecord(eJoin, s2);

    // branch B (main): zero + count/scan (no gemm1 dependency)
    setup_zero_kernel<<<32, 256>>>();
    cs_kernel<<<CS_BLOCKS, CS_THREADS>>>(dst);

    // join: fillw needs el1/er1 (gemm1) AND cursor/rowptr (cs)
    cudaStreamWaitEvent(0, eJoin, 0);

    fillw_kernel<<<(NEDGES / 4 + 255) / 256, 256>>>(src, dst);
    agg1_kernel<<<(NNODES * 32 + 255) / 256, 256>>>(b1);
    gemm2_kernel<<<(NNODES + GM_ROWS - 1) / GM_ROWS, 256>>>(al2, ar2);
    w2e_kernel<<<(NEDGES / 4 + 255) / 256, 256>>>();
    agg2_kernel<<<(NNODES * 32 + 255) / 256, 256>>>(b2, out);
}

// round 16
// speedup vs baseline: 1.1130x; 1.1130x over previous
#include <cuda_runtime.h>
#include <cuda_fp16.h>
#include <math.h>

#define NNODES 100000
#define NEDGES 1600000
#define NEG 0.2f
#define GM_ROWS 128
#define CS_BLOCKS 296
#define CS_THREADS 512

// ---------------- scratch (device globals; no allocation allowed) ----------
__device__ __half g_w1h[128 * 128];               // W1 fp16 transposed [n][k]
__device__ __half g_w2h[32 * 128];                // W2 fp16 transposed [n][k]
__device__ __half g_h1[NNODES * 128];             // layer1 features fp16
__device__ float  g_el1[NNODES * 4];
__device__ float  g_er1[NNODES * 4];
__device__ __half g_x2h[(NNODES + GM_ROWS) * 128];  // layer1 out (elu) fp16, padded
__device__ __half g_h2[NNODES * 32];              // layer2 features fp16
__device__ float  g_el2[NNODES];
__device__ float  g_er2[NNODES];
__device__ int    g_deg[NNODES];
__device__ int    g_rowptr[NNODES + 1];
__device__ int    g_cursor[NNODES];
__device__ int    g_csrc[NEDGES + 64];            // padded; pad never written (=0)
__device__ int    g_cdst[NEDGES + 64];            // padded
__device__ float4 g_w1e[NEDGES + 16];             // layer1 edge weights (4 heads), padded
__device__ float  g_w2e[NEDGES + 64];             // layer2 edge weights, padded
__device__ int    g_bsum[CS_BLOCKS];
__device__ int    g_flags[304];   // [0..295] block flags, [300] sync1

__device__ __forceinline__ unsigned packh2(float a, float b) {
    __half2 h = __floats2half2_rn(a, b);
    return *(unsigned*)&h;
}
__device__ __forceinline__ float edgew(float e) {
    e = (e > 0.f) ? e : NEG * e;
    return __expf(fminf(e, 60.f));
}
__device__ __forceinline__ float elu1(float x) {
    return x > 0.f ? x : (__expf(x) - 1.f);
}

// ---------------- setup -----------------------------------------------------
__global__ __launch_bounds__(256) void setup_zero_kernel() {
    int idx = blockIdx.x * 256 + threadIdx.x;
    int stride = gridDim.x * 256;
    for (int i = idx; i < 25076; i += stride) {
        if (i < 25000) ((int4*)g_deg)[i] = make_int4(0, 0, 0, 0);
        else           ((int4*)g_flags)[i - 25000] = make_int4(0, 0, 0, 0);
    }
}
__global__ __launch_bounds__(256) void setup_conv_kernel(const float* __restrict__ W1,
                                                         const float* __restrict__ W2) {
    int idx = blockIdx.x * 256 + threadIdx.x;
    int stride = gridDim.x * 256;
    for (int i = idx; i < 16384 + 4096; i += stride) {
        if (i < 16384) {
            int k = i >> 7, n = i & 127;
            g_w1h[n * 128 + k] = __float2half_rn(W1[i]);
        } else {
            int j = i - 16384;
            int k = j >> 5, n = j & 31;          // W2: [128][32]
            g_w2h[n * 128 + k] = __float2half_rn(W2[j]);
        }
    }
}

// ---------------- GEMM1 via HMMA: A direct from fp32 x ----------------------
#define WS_STRIDE 136

__global__ __launch_bounds__(256) void gemm1_kernel(
    const float* __restrict__ x, const float* __restrict__ al,
    const float* __restrict__ ar) {
    __shared__ __half ws[128 * WS_STRIDE];  // 34.8 KB: ws[n][k] = W1^T
    int tid = threadIdx.x;
    int nb = blockIdx.x * GM_ROWS;

    for (int i = tid; i < 2048; i += 256) {
        int row = i >> 4, c = i & 15;
        *(uint4*)(ws + row * WS_STRIDE + c * 8) =
            *(const uint4*)(g_w1h + row * 128 + c * 8);
    }
    __syncthreads();

    int l = tid & 31, w = tid >> 5;
    int g4 = l >> 2, q = l & 3;
    int r0 = nb + w * 16 + g4;
    int r1 = r0 + 8;
    const float* xr0 = x + (size_t)(r0 < NNODES ? r0 : NNODES - 1) * 128;
    const float* xr1 = x + (size_t)(r1 < NNODES ? r1 : NNODES - 1) * 128;

    float d[16][4];
#pragma unroll
    for (int nt = 0; nt < 16; ++nt)
#pragma unroll
        for (int c = 0; c < 4; ++c) d[nt][c] = 0.f;

#pragma unroll
    for (int ks = 0; ks < 8; ++ks) {
        int kb = ks * 16 + q * 2;
        float2 f0 = *(const float2*)(xr0 + kb);
        float2 f1 = *(const float2*)(xr1 + kb);
        float2 f2 = *(const float2*)(xr0 + kb + 8);
        float2 f3 = *(const float2*)(xr1 + kb + 8);
        unsigned a0 = packh2(f0.x, f0.y);
        unsigned a1 = packh2(f1.x, f1.y);
        unsigned a2 = packh2(f2.x, f2.y);
        unsigned a3 = packh2(f3.x, f3.y);
#pragma unroll
        for (int nt = 0; nt < 16; ++nt) {
            const __half* wb = ws + (nt * 8 + g4) * WS_STRIDE + kb;
            unsigned b0 = *(const unsigned*)(wb);
            unsigned b1 = *(const unsigned*)(wb + 8);
            asm volatile(
                "mma.sync.aligned.m16n8k16.row.col.f32.f16.f16.f32 "
                "{%0,%1,%2,%3}, {%4,%5,%6,%7}, {%8,%9}, {%0,%1,%2,%3};"
                : "+f"(d[nt][0]), "+f"(d[nt][1]), "+f"(d[nt][2]), "+f"(d[nt][3])
                : "r"(a0), "r"(a1), "r"(a2), "r"(a3), "r"(b0), "r"(b1));
        }
    }

#pragma unroll
    for (int h = 0; h < 4; ++h) {
        float pel0 = 0.f, per0 = 0.f, pel1 = 0.f, per1 = 0.f;
#pragma unroll
        for (int t = 0; t < 4; ++t) {
            int nt = h * 4 + t;
            int c0 = nt * 8 + q * 2;
            float alv0 = __ldg(&al[c0]), alv1 = __ldg(&al[c0 + 1]);
            float arv0 = __ldg(&ar[c0]), arv1 = __ldg(&ar[c0 + 1]);
            pel0 += d[nt][0] * alv0 + d[nt][1] * alv1;
            per0 += d[nt][0] * arv0 + d[nt][1] * arv1;
            pel1 += d[nt][2] * alv0 + d[nt][3] * alv1;
            per1 += d[nt][2] * arv0 + d[nt][3] * arv1;
        }
#pragma unroll
        for (int o = 1; o < 4; o <<= 1) {
            pel0 += __shfl_xor_sync(0xffffffffu, pel0, o);
            per0 += __shfl_xor_sync(0xffffffffu, per0, o);
            pel1 += __shfl_xor_sync(0xffffffffu, pel1, o);
            per1 += __shfl_xor_sync(0xffffffffu, per1, o);
        }
        if (q == 0) {
            if (r0 < NNODES) { g_el1[r0 * 4 + h] = pel0; g_er1[r0 * 4 + h] = per0; }
            if (r1 < NNODES) { g_el1[r1 * 4 + h] = pel1; g_er1[r1 * 4 + h] = per1; }
        }
    }
#pragma unroll
    for (int nt = 0; nt < 16; ++nt) {
        int c0 = nt * 8 + q * 2;
        if (r0 < NNODES)
            ((__half2*)g_h1)[(size_t)r0 * 64 + (c0 >> 1)] =
                __floats2half2_rn(d[nt][0], d[nt][1]);
        if (r1 < NNODES)
            ((__half2*)g_h1)[(size_t)r1 * 64 + (c0 >> 1)] =
                __floats2half2_rn(d[nt][2], d[nt][3]);
    }
}

// ---------------- count + scan (resident grid, one spin-sync) ---------------
__global__ __launch_bounds__(CS_THREADS) void cs_kernel(const int* __restrict__ dst) {
    __shared__ int s[CS_THREADS];
    __shared__ int s_off;
    int b = blockIdx.x, tid = threadIdx.x;
    int gt = b * CS_THREADS + tid;
    const int nthreads = CS_BLOCKS * CS_THREADS;

    for (int i = gt; i < NEDGES / 4; i += nthreads) {
        int4 d = ((const int4*)dst)[i];
        atomicAdd(&g_deg[d.x], 1);
        atomicAdd(&g_deg[d.y], 1);
        atomicAdd(&g_deg[d.z], 1);
        atomicAdd(&g_deg[d.w], 1);
    }
    __threadfence();
    __syncthreads();
    if (tid == 0) {
        atomicAdd(&g_flags[300], 1);
        while (atomicAdd(&g_flags[300], 0) < CS_BLOCKS) {}
    }
    __syncthreads();

    int v = (gt < NNODES) ? g_deg[gt] : 0;
    s[tid] = v;
    if (tid == 0) s_off = 0;
    __syncthreads();
    for (int off = 1; off < CS_THREADS; off <<= 1) {
        int t = (tid >= off) ? s[tid - off] : 0;
        __syncthreads();
        s[tid] += t;
        __syncthreads();
    }
    if (tid == CS_THREADS - 1) {
        g_bsum[b] = s[CS_THREADS - 1];
        __threadfence();
        atomicExch(&g_flags[b], 1);
    }
    if (tid < b) {   // parallel lookback (b < 512)
        while (atomicAdd(&g_flags[tid], 0) == 0) {}
        atomicAdd(&s_off, atomicAdd(&g_bsum[tid], 0));
    }
    __syncthreads();
    if (gt < NNODES) {
        int val = s_off + s[tid];
        g_rowptr[gt + 1] = val;
        if (gt + 1 < NNODES) g_cursor[gt + 1] = val;
    }
    if (gt == 0) { g_rowptr[0] = 0; g_cursor[0] = 0; }
}

// ---------------- fill: csrc only (overlapped with gemm1) -------------------
__global__ __launch_bounds__(256) void fill_kernel(const int* __restrict__ src,
                                                   const int* __restrict__ dst) {
    int i = blockIdx.x * 256 + threadIdx.x;
    if (i >= NEDGES / 4) return;
    int4 d4 = ((const int4*)dst)[i];
    int4 s4 = ((const int4*)src)[i];
    int p0 = atomicAdd(&g_cursor[d4.x], 1);
    int p1 = atomicAdd(&g_cursor[d4.y], 1);
    int p2 = atomicAdd(&g_cursor[d4.z], 1);
    int p3 = atomicAdd(&g_cursor[d4.w], 1);
    g_csrc[p0] = s4.x;
    g_csrc[p1] = s4.y;
    g_csrc[p2] = s4.z;
    g_csrc[p3] = s4.w;
}

// ---------------- cdst from rowptr: contiguous stores (overlapped) ----------
__global__ __launch_bounds__(256) void cdst_kernel() {
    int n = (blockIdx.x * 256 + threadIdx.x) >> 5;
    if (n >= NNODES) return;
    int l = threadIdx.x & 31;
    int s0 = g_rowptr[n], s1 = g_rowptr[n + 1];
    for (int j = s0 + l; j < s1; j += 32) g_cdst[j] = n;
}

// ---------------- layer1 edge weights (contiguous in/out) -------------------
__global__ __launch_bounds__(256) void w1e_kernel() {
    int i = blockIdx.x * 256 + threadIdx.x;
    if (i < NEDGES / 4) {
        int4 s4 = ((const int4*)g_csrc)[i];
        int4 d4 = ((const int4*)g_cdst)[i];
        int ss[4] = {s4.x, s4.y, s4.z, s4.w};
        int dd[4] = {d4.x, d4.y, d4.z, d4.w};
#pragma unroll
        for (int e = 0; e < 4; ++e) {
            float4 el = __ldg((const float4*)&g_el1[ss[e] * 4]);
            float4 er = __ldg((const float4*)&g_er1[dd[e] * 4]);
            float4 w;
            w.x = edgew(el.x + er.x);
            w.y = edgew(el.y + er.y);
            w.z = edgew(el.z + er.z);
            w.w = edgew(el.w + er.w);
            g_w1e[i * 4 + e] = w;
        }
    }
}

// ---------------- layer2 edge weights (after gemm2), edge-parallel ----------
__global__ __launch_bounds__(256) void w2e_kernel() {
    int i = blockIdx.x * 256 + threadIdx.x;
    if (i < NEDGES / 4) {
        int4 s4 = ((const int4*)g_csrc)[i];
        int4 d4 = ((const int4*)g_cdst)[i];
        float4 w;
        w.x = edgew(__ldg(&g_el2[s4.x]) + __ldg(&g_er2[d4.x]));
        w.y = edgew(__ldg(&g_el2[s4.y]) + __ldg(&g_er2[d4.y]));
        w.z = edgew(__ldg(&g_el2[s4.z]) + __ldg(&g_er2[d4.z]));
        w.w = edgew(__ldg(&g_el2[s4.w]) + __ldg(&g_er2[d4.w]));
        ((float4*)g_w2e)[i] = w;
    }
}

// ---------------- AGG layer1: warp/node, precomputed weights ----------------
__global__ __launch_bounds__(256) void agg1_kernel(const float* __restrict__ b1) {
    int n = (blockIdx.x * 256 + threadIdx.x) >> 5;
    if (n >= NNODES) return;
    int l = threadIdx.x & 31;
    int h = l >> 3;
    int s0 = g_rowptr[n], s1 = g_rowptr[n + 1];
    float4 bv = ((const float4*)b1)[l];
    float4 res = bv;
    if (s1 > s0) {
        float sm = 0.f;
        float4 acc = make_float4(0.f, 0.f, 0.f, 0.f);
        const float* wbase = (const float*)g_w1e;
        const uint2* hbase = (const uint2*)g_h1;
        int s = g_csrc[s0];
        for (int j = s0; j < s1; ++j) {
            int snext = __ldg(&g_csrc[j + 1]);   // padded: unconditional
            float wg = __ldg(&wbase[(size_t)j * 4 + h]);
            uint2 p = hbase[(size_t)s * 32 + l];
            float2 f01 = __half22float2(*(__half2*)&p.x);
            float2 f23 = __half22float2(*(__half2*)&p.y);
            sm += wg;
            acc.x = fmaf(wg, f01.x, acc.x);
            acc.y = fmaf(wg, f01.y, acc.y);
            acc.z = fmaf(wg, f23.x, acc.z);
            acc.w = fmaf(wg, f23.y, acc.w);
            s = snext;
        }
        float inv = 1.f / sm;
        res = make_float4(fmaf(acc.x, inv, bv.x), fmaf(acc.y, inv, bv.y),
                          fmaf(acc.z, inv, bv.z), fmaf(acc.w, inv, bv.w));
    }
    res.x = elu1(res.x);
    res.y = elu1(res.y);
    res.z = elu1(res.z);
    res.w = elu1(res.w);
    uint2 u;
    u.x = packh2(res.x, res.y);
    u.y = packh2(res.z, res.w);
    ((uint2*)g_x2h)[(size_t)n * 32 + l] = u;
}

// ---------------- GEMM2 via HMMA: h2 = x2 @ W2, fused el2/er2 ---------------
__global__ __launch_bounds__(256) void gemm2_kernel(
    const float* __restrict__ al, const float* __restrict__ ar) {
    __shared__ __half ws[32 * WS_STRIDE];  // 8.7 KB: ws[n][k] = W2^T
    int tid = threadIdx.x;
    int nb = blockIdx.x * GM_ROWS;

    for (int i = tid; i < 512; i += 256) {
        int row = i >> 4, c = i & 15;
        *(uint4*)(ws + row * WS_STRIDE + c * 8) =
            *(const uint4*)(g_w2h + row * 128 + c * 8);
    }
    __syncthreads();

    int l = tid & 31, w = tid >> 5;
    int g4 = l >> 2, q = l & 3;
    int r0 = nb + w * 16 + g4;
    int r1 = r0 + 8;
    const __half* xr0 = g_x2h + (size_t)r0 * 128;
    const __half* xr1 = g_x2h + (size_t)r1 * 128;

    float d[4][4];
#pragma unroll
    for (int nt = 0; nt < 4; ++nt)
#pragma unroll
        for (int c = 0; c < 4; ++c) d[nt][c] = 0.f;

#pragma unroll
    for (int ks = 0; ks < 8; ++ks) {
        int kb = ks * 16 + q * 2;
        unsigned a0 = *(const unsigned*)(xr0 + kb);
        unsigned a1 = *(const unsigned*)(xr1 + kb);
        unsigned a2 = *(const unsigned*)(xr0 + kb + 8);
        unsigned a3 = *(const unsigned*)(xr1 + kb + 8);
#pragma unroll
        for (int nt = 0; nt < 4; ++nt) {
            const __half* wb = ws + (nt * 8 + g4) * WS_STRIDE + kb;
            unsigned b0 = *(const unsigned*)(wb);
            unsigned b1 = *(const unsigned*)(wb + 8);
            asm volatile(
                "mma.sync.aligned.m16n8k16.row.col.f32.f16.f16.f32 "
                "{%0,%1,%2,%3}, {%4,%5,%6,%7}, {%8,%9}, {%0,%1,%2,%3};"
                : "+f"(d[nt][0]), "+f"(d[nt][1]), "+f"(d[nt][2]), "+f"(d[nt][3])
                : "r"(a0), "r"(a1), "r"(a2), "r"(a3), "r"(b0), "r"(b1));
        }
    }

    {
        float pel0 = 0.f, per0 = 0.f, pel1 = 0.f, per1 = 0.f;
#pragma unroll
        for (int nt = 0; nt < 4; ++nt) {
            int c0 = nt * 8 + q * 2;
            float alv0 = __ldg(&al[c0]), alv1 = __ldg(&al[c0 + 1]);
            float arv0 = __ldg(&ar[c0]), arv1 = __ldg(&ar[c0 + 1]);
            pel0 += d[nt][0] * alv0 + d[nt][1] * alv1;
            per0 += d[nt][0] * arv0 + d[nt][1] * arv1;
            pel1 += d[nt][2] * alv0 + d[nt][3] * alv1;
            per1 += d[nt][2] * arv0 + d[nt][3] * arv1;
        }
#pragma unroll
        for (int o = 1; o < 4; o <<= 1) {
            pel0 += __shfl_xor_sync(0xffffffffu, pel0, o);
            per0 += __shfl_xor_sync(0xffffffffu, per0, o);
            pel1 += __shfl_xor_sync(0xffffffffu, pel1, o);
            per1 += __shfl_xor_sync(0xffffffffu, per1, o);
        }
        if (q == 0) {
            if (r0 < NNODES) { g_el2[r0] = pel0; g_er2[r0] = per0; }
            if (r1 < NNODES) { g_el2[r1] = pel1; g_er2[r1] = per1; }
        }
    }
#pragma unroll
    for (int nt = 0; nt < 4; ++nt) {
        int c0 = nt * 8 + q * 2;
        if (r0 < NNODES)
            ((__half2*)g_h2)[(size_t)r0 * 16 + (c0 >> 1)] =
                __floats2half2_rn(d[nt][0], d[nt][1]);
        if (r1 < NNODES)
            ((__half2*)g_h2)[(size_t)r1 * 16 + (c0 >> 1)] =
                __floats2half2_rn(d[nt][2], d[nt][3]);
    }
}

// ---------------- AGG layer2: warp/node, 4 edges per iteration --------------
__global__ __launch_bounds__(256) void agg2_kernel(const float* __restrict__ b2,
                                                   float* __restrict__ out) {
    int n = (blockIdx.x * 256 + threadIdx.x) >> 5;
    if (n >= NNODES) return;
    int l = threadIdx.x & 31;
    int eo = l >> 3;
    int c4 = l & 7;
    int s0 = g_rowptr[n], s1 = g_rowptr[n + 1];
    float4 bv = ((const float4*)b2)[c4];
    float4 res = bv;
    if (s1 > s0) {
        float sm = 0.f;
        float acc[4];
#pragma unroll
        for (int i = 0; i < 4; ++i) acc[i] = 0.f;
        const uint2* hbase = (const uint2*)g_h2;
        for (int j = s0; j < s1; j += 4) {
            int je = j + eo;
            int se = __ldg(&g_csrc[je]);       // padded
            float wg = __ldg(&g_w2e[je]);      // padded
            if (je >= s1) wg = 0.f;
            uint2 p = __ldg(&hbase[(unsigned)se * 8u + c4]);
            float2 f0 = __half22float2(*(__half2*)&p.x);
            float2 f1 = __half22float2(*(__half2*)&p.y);
            sm += wg;
            acc[0] = fmaf(wg, f0.x, acc[0]);
            acc[1] = fmaf(wg, f0.y, acc[1]);
            acc[2] = fmaf(wg, f1.x, acc[2]);
            acc[3] = fmaf(wg, f1.y, acc[3]);
        }
        sm += __shfl_xor_sync(0xffffffffu, sm, 8);
        sm += __shfl_xor_sync(0xffffffffu, sm, 16);
#pragma unroll
        for (int i = 0; i < 4; ++i) {
            acc[i] += __shfl_xor_sync(0xffffffffu, acc[i], 8);
            acc[i] += __shfl_xor_sync(0xffffffffu, acc[i], 16);
        }
        float inv = 1.f / sm;
        res.x = fmaf(acc[0], inv, bv.x);
        res.y = fmaf(acc[1], inv, bv.y);
        res.z = fmaf(acc[2], inv, bv.z);
        res.w = fmaf(acc[3], inv, bv.w);
    }
    if (eo == 0) {
        ((float4*)out)[(size_t)n * 8 + c4] = res;
    }
}

// ---------------- launch: fork gemm1 path onto a second stream --------------
extern "C" void kernel_launch(void* const* d_in, const int* in_sizes, int n_in,
                              void* d_out, int out_size) {
    const float* x   = (const float*)d_in[0];
    const int*   src = (const int*)d_in[1];
    const int*   dst = (const int*)d_in[2];
    const float* W1  = (const float*)d_in[3];
    const float* al1 = (const float*)d_in[4];
    const float* ar1 = (const float*)d_in[5];
    const float* b1  = (const float*)d_in[6];
    const float* W2  = (const float*)d_in[7];
    const float* al2 = (const float*)d_in[8];
    const float* ar2 = (const float*)d_in[9];
    const float* b2  = (const float*)d_in[10];
    float* out = (float*)d_out;

    // fork-join pair (created per call; NOT destroyed mid-capture — host
    // driver objects only, no device memory)
    cudaStream_t s2;
    cudaStreamCreate(&s2);
    cudaEvent_t eFork, eJoin;
    cudaEventCreateWithFlags(&eFork, cudaEventDisableTiming);
    cudaEventCreateWithFlags(&eJoin, cudaEventDisableTiming);

    cudaEventRecord(eFork, 0);
    cudaStreamWaitEvent(s2, eFork, 0);

    // branch B (main): zero + count/scan + fill + cdst (no gemm1 dependency)
    setup_zero_kernel<<<32, 256>>>();                       // idx 0
    cs_kernel<<<CS_BLOCKS, CS_THREADS>>>(dst);              // idx 1
    // branch A (s2): weight convert + gemm1 (concurrent with branch B)
    setup_conv_kernel<<<16, 256, 0, s2>>>(W1, W2);          // idx 2
    fill_kernel<<<(NEDGES / 4 + 255) / 256, 256>>>(src, dst);  // idx 3: profiled
    gemm1_kernel<<<(NNODES + GM_ROWS - 1) / GM_ROWS, 256, 0, s2>>>(x, al1, ar1);
    cudaEventRecord(eJoin, s2);
    cdst_kernel<<<(NNODES * 32 + 255) / 256, 256>>>();

    // join: w1e needs el1/er1 (gemm1) AND csrc/cdst (branch B)
    cudaStreamWaitEvent(0, eJoin, 0);

    w1e_kernel<<<(NEDGES / 4 + 255) / 256, 256>>>();
    agg1_kernel<<<(NNODES * 32 + 255) / 256, 256>>>(b1);
    gemm2_kernel<<<(NNODES + GM_ROWS - 1) / GM_ROWS, 256>>>(al2, ar2);
    w2e_kernel<<<(NEDGES / 4 + 255) / 256, 256>>>();
    agg2_kernel<<<(NNODES * 32 + 255) / 256, 256>>>(b2, out);
}